// round 8
// baseline (speedup 1.0000x reference)
#include <cuda_runtime.h>
#include <cuda_bf16.h>
#include <math.h>
#include <cstdint>

#define NB   100
#define NC   512
#define NHW  256
#define CHW  (NC*NHW)          // 131072
#define WAYN 5
#define SHOTN 5
#define NQ   75
#define SCALEF 10.0f
#define EPSF 1e-8f

// Scratch (static device globals — no runtime allocation)
__device__ float g_M[NB*CHW];                 // exp(conv logits + bias)
__device__ float g_part[NB*16];               // per-tile partial sum(exp)
__device__ float g_s[WAYN*NC];                // prototypes
__device__ __nv_bfloat16 g_Wh[NC*NC];         // W hi
__device__ __nv_bfloat16 g_Wl[NC*NC];         // W lo
__device__ __nv_bfloat16 g_xh[NB*CHW];        // x hi
__device__ __nv_bfloat16 g_xl[NB*CHW];        // x lo

// ---------------------------------------------------------------------------
// Split helpers
// ---------------------------------------------------------------------------
__device__ __forceinline__ uint32_t pack_bf2(__nv_bfloat16 a, __nv_bfloat16 b) {
    return (uint32_t)__bfloat16_as_ushort(a) | ((uint32_t)__bfloat16_as_ushort(b) << 16);
}

__global__ void split_w(const float* __restrict__ Wm) {
    int i = (blockIdx.x * 256 + threadIdx.x) * 4;
    float4 v = *(const float4*)(Wm + i);
    float vv[4] = {v.x, v.y, v.z, v.w};
    __nv_bfloat16 h[4], l[4];
    #pragma unroll
    for (int j = 0; j < 4; j++) {
        h[j] = __float2bfloat16(vv[j]);
        l[j] = __float2bfloat16(vv[j] - __bfloat162float(h[j]));
    }
    uint2 ph = {pack_bf2(h[0], h[1]), pack_bf2(h[2], h[3])};
    uint2 pl = {pack_bf2(l[0], l[1]), pack_bf2(l[2], l[3])};
    *(uint2*)(g_Wh + i) = ph;
    *(uint2*)(g_Wl + i) = pl;
}

// Half-batch x split (two launches keep gemm as the 4th launch for ncu)
__global__ void split_x(const float* __restrict__ x, int elem_off) {
    size_t i = (size_t)elem_off + ((size_t)blockIdx.x * 256 + threadIdx.x) * 4;
    float4 v = *(const float4*)(x + i);
    float vv[4] = {v.x, v.y, v.z, v.w};
    __nv_bfloat16 h[4], l[4];
    #pragma unroll
    for (int j = 0; j < 4; j++) {
        h[j] = __float2bfloat16(vv[j]);
        l[j] = __float2bfloat16(vv[j] - __bfloat162float(h[j]));
    }
    uint2 ph = {pack_bf2(h[0], h[1]), pack_bf2(h[2], h[3])};
    uint2 pl = {pack_bf2(l[0], l[1]), pack_bf2(l[2], l[3])};
    *(uint2*)(g_xh + i) = ph;
    *(uint2*)(g_xl + i) = pl;
}

// ---------------------------------------------------------------------------
// 1) bf16 mma.sync GEMM (3-term hi/lo), 4-stage cp.async pipeline.
//    CTA tile 128(M) x 64(N) x 32(K), 8 warps (4m x 2n), warp tile 32x32.
//    32-reg accumulator -> 3 CTAs/SM (occupancy-driven retile).
//    Epilogue stores exp(logit+bias) + per-tile partial sums.
// ---------------------------------------------------------------------------
#define KCHUNK   32
#define NCHUNKS  48   // 1536 / 32
#define NSTAGE   4
#define TILE_N   64
#define AS_STRIDE 56
#define BS_STRIDE 72
#define AS_BYTES  (128 * AS_STRIDE * 2)      // 14336
#define BS_BYTES  (32 * BS_STRIDE * 2)       // 4608
#define STAGE_BYTES (AS_BYTES + BS_BYTES)    // 18944
#define GEMM_SMEM (NSTAGE * STAGE_BYTES)     // 75776

__global__ void __launch_bounds__(256, 3) gemm_tc(const float* __restrict__ bias) {
    extern __shared__ __align__(16) char dynsmem[];

    const int tid = threadIdx.x;
    const int wid = tid >> 5, lid = tid & 31;
    const int bn = blockIdx.x * TILE_N;   // n tile offset (hw)
    const int mo = blockIdx.y * 128;      // m tile offset (outC)
    const int b  = blockIdx.z;

    const int warp_m = wid >> 1;          // 0..3
    const int warp_n = wid & 1;           // 0..1
    const int m_base = warp_m * 32;
    const int n_base = warp_n * 32;

    const __nv_bfloat16* xh_b = g_xh + (size_t)b * CHW;
    const __nv_bfloat16* xl_b = g_xl + (size_t)b * CHW;

    float acc[2][4][4] = {};

    auto issue = [&](int chunk, int buf) {
        const int seg = chunk >> 4;
        const int k0  = (chunk & 15) * KCHUNK;
        const __nv_bfloat16* Aw = (seg < 2) ? g_Wh : g_Wl;
        const __nv_bfloat16* Bx = (seg == 1) ? xl_b : xh_b;
        __nv_bfloat16* As = (__nv_bfloat16*)(dynsmem + buf * STAGE_BYTES);
        __nv_bfloat16* Bs = (__nv_bfloat16*)(dynsmem + buf * STAGE_BYTES + AS_BYTES);
        #pragma unroll
        for (int i = 0; i < 2; i++) {           // A: 128 rows x 32 k (512 x 16B)
            int idx = tid + i * 256;
            int row = idx >> 2, s = idx & 3;
            const void* src = Aw + (size_t)(mo + row) * NC + k0 + s * 8;
            uint32_t dst = (uint32_t)__cvta_generic_to_shared(As + row * AS_STRIDE + s * 8);
            asm volatile("cp.async.cg.shared.global [%0], [%1], 16;" :: "r"(dst), "l"(src));
        }
        {                                       // B: 32 k-rows x 64 n (256 x 16B)
            int row = tid >> 3, s = tid & 7;
            const void* src = Bx + (size_t)(k0 + row) * NHW + bn + s * 8;
            uint32_t dst = (uint32_t)__cvta_generic_to_shared(Bs + row * BS_STRIDE + s * 8);
            asm volatile("cp.async.cg.shared.global [%0], [%1], 16;" :: "r"(dst), "l"(src));
        }
        asm volatile("cp.async.commit_group;");
    };

    issue(0, 0);
    issue(1, 1);
    issue(2, 2);

    int buf = 0;
    for (int c = 0; c < NCHUNKS; c++) {
        if (c >= NCHUNKS - 1)      asm volatile("cp.async.wait_group 0;");
        else if (c == NCHUNKS - 2) asm volatile("cp.async.wait_group 1;");
        else                       asm volatile("cp.async.wait_group 2;");
        __syncthreads();
        if (c + 3 < NCHUNKS) {
            int nb = buf + 3; if (nb >= NSTAGE) nb -= NSTAGE;
            issue(c + 3, nb);
        }

        const __nv_bfloat16* As = (const __nv_bfloat16*)(dynsmem + buf * STAGE_BYTES);
        const __nv_bfloat16* Bs = (const __nv_bfloat16*)(dynsmem + buf * STAGE_BYTES + AS_BYTES);

        #pragma unroll
        for (int kk = 0; kk < 2; kk++) {
            const int k16 = kk * 16;
            uint32_t af[2][4];
            #pragma unroll
            for (int mi = 0; mi < 2; mi++) {
                uint32_t addr = (uint32_t)__cvta_generic_to_shared(
                    As + (m_base + mi * 16 + (lid & 15)) * AS_STRIDE + k16 + (lid >> 4) * 8);
                asm volatile("ldmatrix.sync.aligned.m8n8.x4.shared.b16 {%0,%1,%2,%3}, [%4];"
                    : "=r"(af[mi][0]), "=r"(af[mi][1]), "=r"(af[mi][2]), "=r"(af[mi][3])
                    : "r"(addr));
            }
            uint32_t bfr[4][2];
            #pragma unroll
            for (int njp = 0; njp < 2; njp++) {
                uint32_t addr = (uint32_t)__cvta_generic_to_shared(
                    Bs + (k16 + (lid & 15)) * BS_STRIDE + n_base + njp * 16 + (lid >> 4) * 8);
                asm volatile("ldmatrix.sync.aligned.m8n8.x4.trans.shared.b16 {%0,%1,%2,%3}, [%4];"
                    : "=r"(bfr[2*njp][0]), "=r"(bfr[2*njp][1]),
                      "=r"(bfr[2*njp+1][0]), "=r"(bfr[2*njp+1][1])
                    : "r"(addr));
            }
            #pragma unroll
            for (int mi = 0; mi < 2; mi++)
                #pragma unroll
                for (int nj = 0; nj < 4; nj++)
                    asm volatile(
                        "mma.sync.aligned.m16n8k16.row.col.f32.bf16.bf16.f32 "
                        "{%0,%1,%2,%3}, {%4,%5,%6,%7}, {%8,%9}, {%0,%1,%2,%3};"
                        : "+f"(acc[mi][nj][0]), "+f"(acc[mi][nj][1]),
                          "+f"(acc[mi][nj][2]), "+f"(acc[mi][nj][3])
                        : "r"(af[mi][0]), "r"(af[mi][1]), "r"(af[mi][2]), "r"(af[mi][3]),
                          "r"(bfr[nj][0]), "r"(bfr[nj][1]));
        }
        buf++; if (buf == NSTAGE) buf = 0;
    }

    // Epilogue: store exp(logit + bias), fused partial sum(exp)
    float* Mb = g_M + (size_t)b * CHW;
    float esum = 0.f;
    #pragma unroll
    for (int mi = 0; mi < 2; mi++) {
        int r0 = mo + m_base + mi * 16 + (lid >> 2);
        float b0 = bias[r0], b1 = bias[r0 + 8];
        #pragma unroll
        for (int nj = 0; nj < 4; nj++) {
            int col = bn + n_base + nj * 8 + (lid & 3) * 2;
            float e00 = __expf(acc[mi][nj][0] + b0);
            float e01 = __expf(acc[mi][nj][1] + b0);
            float e10 = __expf(acc[mi][nj][2] + b1);
            float e11 = __expf(acc[mi][nj][3] + b1);
            esum += e00 + e01 + e10 + e11;
            *(float2*)(Mb + (size_t)r0 * NHW + col) = make_float2(e00, e01);
            *(float2*)(Mb + (size_t)(r0 + 8) * NHW + col) = make_float2(e10, e11);
        }
    }
    __syncthreads();                 // all async groups done; safe to reuse smem
    float* red = (float*)dynsmem;
    red[tid] = esum;
    __syncthreads();
    for (int s = 128; s > 0; s >>= 1) {
        if (tid < s) red[tid] += red[tid + s];
        __syncthreads();
    }
    if (tid == 0)
        g_part[b * 16 + blockIdx.y * 4 + blockIdx.x] = red[0];
}

// ---------------------------------------------------------------------------
// 2) Prototypes with fused mask: s[m,d] = mean over shots,hw of x*Me*inv_sb
// ---------------------------------------------------------------------------
__global__ void protos(const float* __restrict__ x) {
    __shared__ float inv_sm[SHOTN];
    __shared__ float sdata[128];
    const int m = blockIdx.x;
    const int d = blockIdx.y;

    if (threadIdx.x < SHOTN) {
        float s = 0.f;
        #pragma unroll
        for (int t = 0; t < 16; t++) s += g_part[(m * 20 + threadIdx.x) * 16 + t];
        inv_sm[threadIdx.x] = 1.f / s;
    }
    __syncthreads();

    float sum = 0.f;
    for (int l = threadIdx.x; l < SHOTN * NHW; l += 128) {
        int sb = l >> 8, hw = l & 255;
        size_t idx = (size_t)(m * 20 + sb) * CHW + (size_t)d * NHW + hw;
        sum += x[idx] * g_M[idx] * inv_sm[sb];
    }
    sdata[threadIdx.x] = sum;
    __syncthreads();
    for (int s = 64; s > 0; s >>= 1) {
        if (threadIdx.x < s) sdata[threadIdx.x] += sdata[threadIdx.x + s];
        __syncthreads();
    }
    if (threadIdx.x == 0)
        g_s[m * NC + d] = sdata[0] * (1.f / (SHOTN * NHW));
}

// ---------------------------------------------------------------------------
// 3) Cosine scores + class softmax + spatial mean. 1 block (1024 thr) / query.
//    Mask normalizer cancels in cosine -> qv = x * exp(M), no inv needed.
// ---------------------------------------------------------------------------
__global__ void __launch_bounds__(1024) scores_kernel(const float* __restrict__ x,
                                                      float* __restrict__ out) {
    __shared__ float s_sm[WAYN * NC];        // 10 KB
    __shared__ float sn_sm[WAYN];
    __shared__ float part[6][4][256];        // 24 KB
    __shared__ float red[256];

    const int n  = blockIdx.x;
    const int m0 = n / 15;
    const int qi = n - m0 * 15;
    const int bq = m0 * 20 + SHOTN + qi;
    const int tid = threadIdx.x;

    for (int l = tid; l < WAYN * NC; l += 1024) s_sm[l] = g_s[l];
    __syncthreads();

    // warps 0..4: warp w reduces ||s[w]||
    const int wid = tid >> 5, lid = tid & 31;
    if (wid < WAYN) {
        float a = 0.f;
        #pragma unroll
        for (int j = 0; j < NC / 32; j++) {
            float v = s_sm[wid * NC + j * 32 + lid];
            a += v * v;
        }
        #pragma unroll
        for (int o = 16; o > 0; o >>= 1)
            a += __shfl_xor_sync(0xffffffff, a, o);
        if (lid == 0) sn_sm[wid] = fmaxf(sqrtf(a), EPSF);
    }

    const int f = tid & 255;
    const int slice = tid >> 8;              // 0..3
    const float* xb = x + (size_t)bq * CHW;
    const float* Mb = g_M + (size_t)bq * CHW;

    float dot[WAYN] = {};
    float q2 = 0.f;
    const int d0 = slice * 128;
    for (int d = d0; d < d0 + 128; d++) {
        size_t idx = (size_t)d * NHW + f;
        float qv = xb[idx] * Mb[idx];
        q2 += qv * qv;
        #pragma unroll
        for (int m = 0; m < WAYN; m++)
            dot[m] += qv * s_sm[m * NC + d];
    }
    part[0][slice][f] = q2;
    #pragma unroll
    for (int m = 0; m < WAYN; m++) part[1 + m][slice][f] = dot[m];
    __syncthreads();

    float eprob[WAYN];
    if (slice == 0) {
        q2 = part[0][0][f] + part[0][1][f] + part[0][2][f] + part[0][3][f];
        #pragma unroll
        for (int m = 0; m < WAYN; m++)
            dot[m] = part[1+m][0][f] + part[1+m][1][f] + part[1+m][2][f] + part[1+m][3][f];
        const float qn = fmaxf(sqrtf(q2), EPSF);
        float sc[WAYN], mxv = -3.4e38f;
        #pragma unroll
        for (int m = 0; m < WAYN; m++) {
            sc[m] = SCALEF * dot[m] / (qn * sn_sm[m]);
            mxv = fmaxf(mxv, sc[m]);
        }
        float ssum = 0.f;
        #pragma unroll
        for (int m = 0; m < WAYN; m++) { eprob[m] = __expf(sc[m] - mxv); ssum += eprob[m]; }
        const float inv = 1.f / ssum;
        #pragma unroll
        for (int m = 0; m < WAYN; m++) eprob[m] *= inv;
    }

    for (int m = 0; m < WAYN; m++) {
        __syncthreads();
        if (slice == 0) red[f] = eprob[m];
        __syncthreads();
        for (int st = 128; st > 0; st >>= 1) {
            if (tid < st) red[tid] += red[tid + st];
            __syncthreads();
        }
        if (tid == 0) out[n * WAYN + m] = red[0] * (1.f / NHW);
    }
}

// ---------------------------------------------------------------------------
extern "C" void kernel_launch(void* const* d_in, const int* in_sizes, int n_in,
                              void* d_out, int out_size) {
    const float* x    = (const float*)d_in[0];   // (100, 512, 16, 16)
    const float* Wm   = (const float*)d_in[1];   // (512, 512)
    const float* bias = (const float*)d_in[2];   // (512,)
    float* out = (float*)d_out;                  // (75, 5)

    static int smem_set = 0;
    if (!smem_set) {
        cudaFuncSetAttribute(gemm_tc, cudaFuncAttributeMaxDynamicSharedMemorySize, GEMM_SMEM);
        smem_set = 1;
    }

    const int half_elems = NB * CHW / 2;
    split_w<<<NC * NC / 1024, 256>>>(Wm);
    split_x<<<half_elems / 1024, 256>>>(x, 0);
    split_x<<<half_elems / 1024, 256>>>(x, half_elems);
    gemm_tc<<<dim3(NHW / TILE_N, NC / 128, NB), 256, GEMM_SMEM>>>(bias);  // 4th launch
    protos<<<dim3(WAYN, NC), 128>>>(x);
    scores_kernel<<<NQ, 1024>>>(x, out);
}

// round 9
// speedup vs baseline: 1.3189x; 1.3189x over previous
#include <cuda_runtime.h>
#include <cuda_bf16.h>
#include <math.h>
#include <cstdint>

#define NB   100
#define NC   512
#define NHW  256
#define CHW  (NC*NHW)          // 131072
#define WAYN 5
#define SHOTN 5
#define NQ   75
#define SCALEF 10.0f
#define EPSF 1e-8f

// Scratch (static device globals — no runtime allocation)
__device__ float g_M[NB*CHW];                 // exp(conv logits + bias)
__device__ float g_part[NB*8];                // per-tile partial sum(exp)
__device__ float g_s[WAYN*NC];                // prototypes
__device__ __nv_bfloat16 g_Wh[NC*NC];         // W hi
__device__ __nv_bfloat16 g_Wl[NC*NC];         // W lo
__device__ __nv_bfloat16 g_xh[NB*CHW];        // x hi (lo term dropped; see notes)

// ---------------------------------------------------------------------------
// Split helpers
// ---------------------------------------------------------------------------
__device__ __forceinline__ uint32_t pack_bf2(__nv_bfloat16 a, __nv_bfloat16 b) {
    return (uint32_t)__bfloat16_as_ushort(a) | ((uint32_t)__bfloat16_as_ushort(b) << 16);
}

__global__ void split_w(const float* __restrict__ Wm) {
    int i = (blockIdx.x * 256 + threadIdx.x) * 4;
    float4 v = *(const float4*)(Wm + i);
    float vv[4] = {v.x, v.y, v.z, v.w};
    __nv_bfloat16 h[4], l[4];
    #pragma unroll
    for (int j = 0; j < 4; j++) {
        h[j] = __float2bfloat16(vv[j]);
        l[j] = __float2bfloat16(vv[j] - __bfloat162float(h[j]));
    }
    uint2 ph = {pack_bf2(h[0], h[1]), pack_bf2(h[2], h[3])};
    uint2 pl = {pack_bf2(l[0], l[1]), pack_bf2(l[2], l[3])};
    *(uint2*)(g_Wh + i) = ph;
    *(uint2*)(g_Wl + i) = pl;
}

// Half-batch x split, hi only (two launches keep gemm as the 4th launch for ncu)
__global__ void split_x(const float* __restrict__ x, int elem_off) {
    size_t i = (size_t)elem_off + ((size_t)blockIdx.x * 256 + threadIdx.x) * 4;
    float4 v = *(const float4*)(x + i);
    uint2 ph = {pack_bf2(__float2bfloat16(v.x), __float2bfloat16(v.y)),
                pack_bf2(__float2bfloat16(v.z), __float2bfloat16(v.w))};
    *(uint2*)(g_xh + i) = ph;
}

// ---------------------------------------------------------------------------
// 1) bf16 mma.sync GEMM, 2-term hi/lo on W only: W*xh = Wh*xh + Wl*xh.
//    K' = 1024 (2 segments x 512). 3-stage cp.async pipeline.
//    CTA tile 128(M) x 128(N) x 32(K), 8 warps (2m x 4n), warp tile 64x32.
//    Epilogue stores exp(logit+bias) and per-tile partial sums.
// ---------------------------------------------------------------------------
#define KCHUNK   32
#define NCHUNKS  32   // 1024 / 32
#define AS_STRIDE 56
#define BS_STRIDE 136
#define AS_BYTES  (128 * AS_STRIDE * 2)      // 14336
#define BS_BYTES  (32 * BS_STRIDE * 2)       // 8704
#define STAGE_BYTES (AS_BYTES + BS_BYTES)    // 23040
#define GEMM_SMEM (3 * STAGE_BYTES)          // 69120

__global__ void __launch_bounds__(256) gemm_tc(const float* __restrict__ bias) {
    extern __shared__ __align__(16) char dynsmem[];

    const int tid = threadIdx.x;
    const int wid = tid >> 5, lid = tid & 31;
    const int bn = blockIdx.x * 128;      // n tile offset (hw)
    const int mo = blockIdx.y * 128;      // m tile offset (outC)
    const int b  = blockIdx.z;

    const int warp_m = wid >> 2;          // 0..1
    const int warp_n = wid & 3;           // 0..3
    const int m_base = warp_m * 64;
    const int n_base = warp_n * 32;

    const __nv_bfloat16* xh_b = g_xh + (size_t)b * CHW;

    float acc[4][4][4] = {};

    auto issue = [&](int chunk, int buf) {
        const int seg = chunk >> 4;                       // 0: Wh, 1: Wl
        const int k0  = (chunk & 15) * KCHUNK;
        const __nv_bfloat16* Aw = (seg == 0) ? g_Wh : g_Wl;
        __nv_bfloat16* As = (__nv_bfloat16*)(dynsmem + buf * STAGE_BYTES);
        __nv_bfloat16* Bs = (__nv_bfloat16*)(dynsmem + buf * STAGE_BYTES + AS_BYTES);
        #pragma unroll
        for (int i = 0; i < 2; i++) {           // A: 128 rows x 32 k
            int idx = tid + i * 256;
            int row = idx >> 2, s = idx & 3;
            const void* src = Aw + (size_t)(mo + row) * NC + k0 + s * 8;
            uint32_t dst = (uint32_t)__cvta_generic_to_shared(As + row * AS_STRIDE + s * 8);
            asm volatile("cp.async.cg.shared.global [%0], [%1], 16;" :: "r"(dst), "l"(src));
        }
        #pragma unroll
        for (int i = 0; i < 2; i++) {           // B: 32 k-rows x 128 n
            int idx = tid + i * 256;
            int row = idx >> 4, s = idx & 15;
            const void* src = xh_b + (size_t)(k0 + row) * NHW + bn + s * 8;
            uint32_t dst = (uint32_t)__cvta_generic_to_shared(Bs + row * BS_STRIDE + s * 8);
            asm volatile("cp.async.cg.shared.global [%0], [%1], 16;" :: "r"(dst), "l"(src));
        }
        asm volatile("cp.async.commit_group;");
    };

    issue(0, 0);
    issue(1, 1);

    int buf = 0;
    for (int c = 0; c < NCHUNKS; c++) {
        if (c == NCHUNKS - 1) asm volatile("cp.async.wait_group 0;");
        else                  asm volatile("cp.async.wait_group 1;");
        __syncthreads();
        if (c + 2 < NCHUNKS) {
            int nb = buf + 2; if (nb >= 3) nb -= 3;
            issue(c + 2, nb);
        }

        const __nv_bfloat16* As = (const __nv_bfloat16*)(dynsmem + buf * STAGE_BYTES);
        const __nv_bfloat16* Bs = (const __nv_bfloat16*)(dynsmem + buf * STAGE_BYTES + AS_BYTES);

        #pragma unroll
        for (int kk = 0; kk < 2; kk++) {
            const int k16 = kk * 16;
            uint32_t af[4][4];
            #pragma unroll
            for (int mi = 0; mi < 4; mi++) {
                uint32_t addr = (uint32_t)__cvta_generic_to_shared(
                    As + (m_base + mi * 16 + (lid & 15)) * AS_STRIDE + k16 + (lid >> 4) * 8);
                asm volatile("ldmatrix.sync.aligned.m8n8.x4.shared.b16 {%0,%1,%2,%3}, [%4];"
                    : "=r"(af[mi][0]), "=r"(af[mi][1]), "=r"(af[mi][2]), "=r"(af[mi][3])
                    : "r"(addr));
            }
            uint32_t bfr[4][2];
            #pragma unroll
            for (int njp = 0; njp < 2; njp++) {
                uint32_t addr = (uint32_t)__cvta_generic_to_shared(
                    Bs + (k16 + (lid & 15)) * BS_STRIDE + n_base + njp * 16 + (lid >> 4) * 8);
                asm volatile("ldmatrix.sync.aligned.m8n8.x4.trans.shared.b16 {%0,%1,%2,%3}, [%4];"
                    : "=r"(bfr[2*njp][0]), "=r"(bfr[2*njp][1]),
                      "=r"(bfr[2*njp+1][0]), "=r"(bfr[2*njp+1][1])
                    : "r"(addr));
            }
            #pragma unroll
            for (int mi = 0; mi < 4; mi++)
                #pragma unroll
                for (int nj = 0; nj < 4; nj++)
                    asm volatile(
                        "mma.sync.aligned.m16n8k16.row.col.f32.bf16.bf16.f32 "
                        "{%0,%1,%2,%3}, {%4,%5,%6,%7}, {%8,%9}, {%0,%1,%2,%3};"
                        : "+f"(acc[mi][nj][0]), "+f"(acc[mi][nj][1]),
                          "+f"(acc[mi][nj][2]), "+f"(acc[mi][nj][3])
                        : "r"(af[mi][0]), "r"(af[mi][1]), "r"(af[mi][2]), "r"(af[mi][3]),
                          "r"(bfr[nj][0]), "r"(bfr[nj][1]));
        }
        buf++; if (buf == 3) buf = 0;
    }

    // Epilogue: store exp(logit + bias), fused partial sum(exp)
    float* Mb = g_M + (size_t)b * CHW;
    float esum = 0.f;
    #pragma unroll
    for (int mi = 0; mi < 4; mi++) {
        int r0 = mo + m_base + mi * 16 + (lid >> 2);
        float b0 = bias[r0], b1 = bias[r0 + 8];
        #pragma unroll
        for (int nj = 0; nj < 4; nj++) {
            int col = bn + n_base + nj * 8 + (lid & 3) * 2;
            float e00 = __expf(acc[mi][nj][0] + b0);
            float e01 = __expf(acc[mi][nj][1] + b0);
            float e10 = __expf(acc[mi][nj][2] + b1);
            float e11 = __expf(acc[mi][nj][3] + b1);
            esum += e00 + e01 + e10 + e11;
            *(float2*)(Mb + (size_t)r0 * NHW + col) = make_float2(e00, e01);
            *(float2*)(Mb + (size_t)(r0 + 8) * NHW + col) = make_float2(e10, e11);
        }
    }
    __syncthreads();                 // all async groups done; safe to reuse smem
    float* red = (float*)dynsmem;
    red[tid] = esum;
    __syncthreads();
    for (int s = 128; s > 0; s >>= 1) {
        if (tid < s) red[tid] += red[tid + s];
        __syncthreads();
    }
    if (tid == 0)
        g_part[b * 8 + blockIdx.y * 2 + blockIdx.x] = red[0];
}

// ---------------------------------------------------------------------------
// 2) Prototypes with fused mask: s[m,d] = mean over shots,hw of x*Me*inv_sb
// ---------------------------------------------------------------------------
__global__ void protos(const float* __restrict__ x) {
    __shared__ float inv_sm[SHOTN];
    __shared__ float sdata[128];
    const int m = blockIdx.x;
    const int d = blockIdx.y;

    if (threadIdx.x < SHOTN) {
        float s = 0.f;
        #pragma unroll
        for (int t = 0; t < 8; t++) s += g_part[(m * 20 + threadIdx.x) * 8 + t];
        inv_sm[threadIdx.x] = 1.f / s;
    }
    __syncthreads();

    float sum = 0.f;
    for (int l = threadIdx.x; l < SHOTN * NHW; l += 128) {
        int sb = l >> 8, hw = l & 255;
        size_t idx = (size_t)(m * 20 + sb) * CHW + (size_t)d * NHW + hw;
        sum += x[idx] * g_M[idx] * inv_sm[sb];
    }
    sdata[threadIdx.x] = sum;
    __syncthreads();
    for (int s = 64; s > 0; s >>= 1) {
        if (threadIdx.x < s) sdata[threadIdx.x] += sdata[threadIdx.x + s];
        __syncthreads();
    }
    if (threadIdx.x == 0)
        g_s[m * NC + d] = sdata[0] * (1.f / (SHOTN * NHW));
}

// ---------------------------------------------------------------------------
// 3) Cosine scores + class softmax + spatial mean. 1 block (1024 thr) / query.
//    Mask normalizer cancels in cosine -> qv = x * exp(M), no inv needed.
// ---------------------------------------------------------------------------
__global__ void __launch_bounds__(1024) scores_kernel(const float* __restrict__ x,
                                                      float* __restrict__ out) {
    __shared__ float s_sm[WAYN * NC];        // 10 KB
    __shared__ float sn_sm[WAYN];
    __shared__ float part[6][4][256];        // 24 KB
    __shared__ float red[256];

    const int n  = blockIdx.x;
    const int m0 = n / 15;
    const int qi = n - m0 * 15;
    const int bq = m0 * 20 + SHOTN + qi;
    const int tid = threadIdx.x;

    for (int l = tid; l < WAYN * NC; l += 1024) s_sm[l] = g_s[l];
    __syncthreads();

    // warps 0..4: warp w reduces ||s[w]||
    const int wid = tid >> 5, lid = tid & 31;
    if (wid < WAYN) {
        float a = 0.f;
        #pragma unroll
        for (int j = 0; j < NC / 32; j++) {
            float v = s_sm[wid * NC + j * 32 + lid];
            a += v * v;
        }
        #pragma unroll
        for (int o = 16; o > 0; o >>= 1)
            a += __shfl_xor_sync(0xffffffff, a, o);
        if (lid == 0) sn_sm[wid] = fmaxf(sqrtf(a), EPSF);
    }

    const int f = tid & 255;
    const int slice = tid >> 8;              // 0..3
    const float* xb = x + (size_t)bq * CHW;
    const float* Mb = g_M + (size_t)bq * CHW;

    float dot[WAYN] = {};
    float q2 = 0.f;
    const int d0 = slice * 128;
    for (int d = d0; d < d0 + 128; d++) {
        size_t idx = (size_t)d * NHW + f;
        float qv = xb[idx] * Mb[idx];
        q2 += qv * qv;
        #pragma unroll
        for (int m = 0; m < WAYN; m++)
            dot[m] += qv * s_sm[m * NC + d];
    }
    part[0][slice][f] = q2;
    #pragma unroll
    for (int m = 0; m < WAYN; m++) part[1 + m][slice][f] = dot[m];
    __syncthreads();

    float eprob[WAYN];
    if (slice == 0) {
        q2 = part[0][0][f] + part[0][1][f] + part[0][2][f] + part[0][3][f];
        #pragma unroll
        for (int m = 0; m < WAYN; m++)
            dot[m] = part[1+m][0][f] + part[1+m][1][f] + part[1+m][2][f] + part[1+m][3][f];
        const float qn = fmaxf(sqrtf(q2), EPSF);
        float sc[WAYN], mxv = -3.4e38f;
        #pragma unroll
        for (int m = 0; m < WAYN; m++) {
            sc[m] = SCALEF * dot[m] / (qn * sn_sm[m]);
            mxv = fmaxf(mxv, sc[m]);
        }
        float ssum = 0.f;
        #pragma unroll
        for (int m = 0; m < WAYN; m++) { eprob[m] = __expf(sc[m] - mxv); ssum += eprob[m]; }
        const float inv = 1.f / ssum;
        #pragma unroll
        for (int m = 0; m < WAYN; m++) eprob[m] *= inv;
    }

    for (int m = 0; m < WAYN; m++) {
        __syncthreads();
        if (slice == 0) red[f] = eprob[m];
        __syncthreads();
        for (int st = 128; st > 0; st >>= 1) {
            if (tid < st) red[tid] += red[tid + st];
            __syncthreads();
        }
        if (tid == 0) out[n * WAYN + m] = red[0] * (1.f / NHW);
    }
}

// ---------------------------------------------------------------------------
extern "C" void kernel_launch(void* const* d_in, const int* in_sizes, int n_in,
                              void* d_out, int out_size) {
    const float* x    = (const float*)d_in[0];   // (100, 512, 16, 16)
    const float* Wm   = (const float*)d_in[1];   // (512, 512)
    const float* bias = (const float*)d_in[2];   // (512,)
    float* out = (float*)d_out;                  // (75, 5)

    static int smem_set = 0;
    if (!smem_set) {
        cudaFuncSetAttribute(gemm_tc, cudaFuncAttributeMaxDynamicSharedMemorySize, GEMM_SMEM);
        smem_set = 1;
    }

    const int half_elems = NB * CHW / 2;
    split_w<<<NC * NC / 1024, 256>>>(Wm);
    split_x<<<half_elems / 1024, 256>>>(x, 0);
    split_x<<<half_elems / 1024, 256>>>(x, half_elems);
    gemm_tc<<<dim3(NHW / 128, NC / 128, NB), 256, GEMM_SMEM>>>(bias);  // 4th launch
    protos<<<dim3(WAYN, NC), 128>>>(x);
    scores_kernel<<<NQ, 1024>>>(x, out);
}

// round 10
// speedup vs baseline: 1.7147x; 1.3001x over previous
#include <cuda_runtime.h>
#include <cuda_bf16.h>
#include <math.h>
#include <cstdint>

#define NB   100
#define NC   512
#define NHW  256
#define CHW  (NC*NHW)          // 131072
#define WAYN 5
#define SHOTN 5
#define NQ   75
#define SCALEF 10.0f
#define EPSF 1e-8f

// Scratch (static device globals — no runtime allocation)
__device__ float g_M[NB*CHW];                 // exp(conv logits + bias)
__device__ float g_part[NB*8];                // per-tile partial sum(exp)
__device__ float g_s[WAYN*NC];                // prototypes
__device__ __nv_bfloat16 g_Wh[NC*NC];         // W (bf16)
__device__ __nv_bfloat16 g_xh[NB*CHW];        // x (bf16)

// ---------------------------------------------------------------------------
// bf16 conversion kernels
// ---------------------------------------------------------------------------
__device__ __forceinline__ uint32_t pack_bf2(__nv_bfloat16 a, __nv_bfloat16 b) {
    return (uint32_t)__bfloat16_as_ushort(a) | ((uint32_t)__bfloat16_as_ushort(b) << 16);
}

__global__ void split_w(const float* __restrict__ Wm) {
    int i = (blockIdx.x * 256 + threadIdx.x) * 4;
    float4 v = *(const float4*)(Wm + i);
    uint2 ph = {pack_bf2(__float2bfloat16(v.x), __float2bfloat16(v.y)),
                pack_bf2(__float2bfloat16(v.z), __float2bfloat16(v.w))};
    *(uint2*)(g_Wh + i) = ph;
}

// Half-batch x convert (two launches keep gemm as the 4th launch for ncu)
__global__ void split_x(const float* __restrict__ x, int elem_off) {
    size_t i = (size_t)elem_off + ((size_t)blockIdx.x * 256 + threadIdx.x) * 4;
    float4 v = *(const float4*)(x + i);
    uint2 ph = {pack_bf2(__float2bfloat16(v.x), __float2bfloat16(v.y)),
                pack_bf2(__float2bfloat16(v.z), __float2bfloat16(v.w))};
    *(uint2*)(g_xh + i) = ph;
}

// ---------------------------------------------------------------------------
// 1) Pure bf16 mma.sync GEMM, K = 512. 3-stage cp.async pipeline.
//    CTA tile 128(M) x 128(N) x 32(K), 8 warps (2m x 4n), warp tile 64x32.
//    Epilogue stores exp(logit+bias) and per-tile partial sums.
// ---------------------------------------------------------------------------
#define KCHUNK   32
#define NCHUNKS  16   // 512 / 32
#define AS_STRIDE 56
#define BS_STRIDE 136
#define AS_BYTES  (128 * AS_STRIDE * 2)      // 14336
#define BS_BYTES  (32 * BS_STRIDE * 2)       // 8704
#define STAGE_BYTES (AS_BYTES + BS_BYTES)    // 23040
#define GEMM_SMEM (3 * STAGE_BYTES)          // 69120

__global__ void __launch_bounds__(256) gemm_tc(const float* __restrict__ bias) {
    extern __shared__ __align__(16) char dynsmem[];

    const int tid = threadIdx.x;
    const int wid = tid >> 5, lid = tid & 31;
    const int bn = blockIdx.x * 128;      // n tile offset (hw)
    const int mo = blockIdx.y * 128;      // m tile offset (outC)
    const int b  = blockIdx.z;

    const int warp_m = wid >> 2;          // 0..1
    const int warp_n = wid & 3;           // 0..3
    const int m_base = warp_m * 64;
    const int n_base = warp_n * 32;

    const __nv_bfloat16* xh_b = g_xh + (size_t)b * CHW;

    float acc[4][4][4] = {};

    auto issue = [&](int chunk, int buf) {
        const int k0 = chunk * KCHUNK;
        __nv_bfloat16* As = (__nv_bfloat16*)(dynsmem + buf * STAGE_BYTES);
        __nv_bfloat16* Bs = (__nv_bfloat16*)(dynsmem + buf * STAGE_BYTES + AS_BYTES);
        #pragma unroll
        for (int i = 0; i < 2; i++) {           // A: 128 rows x 32 k
            int idx = tid + i * 256;
            int row = idx >> 2, s = idx & 3;
            const void* src = g_Wh + (size_t)(mo + row) * NC + k0 + s * 8;
            uint32_t dst = (uint32_t)__cvta_generic_to_shared(As + row * AS_STRIDE + s * 8);
            asm volatile("cp.async.cg.shared.global [%0], [%1], 16;" :: "r"(dst), "l"(src));
        }
        #pragma unroll
        for (int i = 0; i < 2; i++) {           // B: 32 k-rows x 128 n
            int idx = tid + i * 256;
            int row = idx >> 4, s = idx & 15;
            const void* src = xh_b + (size_t)(k0 + row) * NHW + bn + s * 8;
            uint32_t dst = (uint32_t)__cvta_generic_to_shared(Bs + row * BS_STRIDE + s * 8);
            asm volatile("cp.async.cg.shared.global [%0], [%1], 16;" :: "r"(dst), "l"(src));
        }
        asm volatile("cp.async.commit_group;");
    };

    issue(0, 0);
    issue(1, 1);

    int buf = 0;
    for (int c = 0; c < NCHUNKS; c++) {
        if (c == NCHUNKS - 1) asm volatile("cp.async.wait_group 0;");
        else                  asm volatile("cp.async.wait_group 1;");
        __syncthreads();
        if (c + 2 < NCHUNKS) {
            int nb = buf + 2; if (nb >= 3) nb -= 3;
            issue(c + 2, nb);
        }

        const __nv_bfloat16* As = (const __nv_bfloat16*)(dynsmem + buf * STAGE_BYTES);
        const __nv_bfloat16* Bs = (const __nv_bfloat16*)(dynsmem + buf * STAGE_BYTES + AS_BYTES);

        #pragma unroll
        for (int kk = 0; kk < 2; kk++) {
            const int k16 = kk * 16;
            uint32_t af[4][4];
            #pragma unroll
            for (int mi = 0; mi < 4; mi++) {
                uint32_t addr = (uint32_t)__cvta_generic_to_shared(
                    As + (m_base + mi * 16 + (lid & 15)) * AS_STRIDE + k16 + (lid >> 4) * 8);
                asm volatile("ldmatrix.sync.aligned.m8n8.x4.shared.b16 {%0,%1,%2,%3}, [%4];"
                    : "=r"(af[mi][0]), "=r"(af[mi][1]), "=r"(af[mi][2]), "=r"(af[mi][3])
                    : "r"(addr));
            }
            uint32_t bfr[4][2];
            #pragma unroll
            for (int njp = 0; njp < 2; njp++) {
                uint32_t addr = (uint32_t)__cvta_generic_to_shared(
                    Bs + (k16 + (lid & 15)) * BS_STRIDE + n_base + njp * 16 + (lid >> 4) * 8);
                asm volatile("ldmatrix.sync.aligned.m8n8.x4.trans.shared.b16 {%0,%1,%2,%3}, [%4];"
                    : "=r"(bfr[2*njp][0]), "=r"(bfr[2*njp][1]),
                      "=r"(bfr[2*njp+1][0]), "=r"(bfr[2*njp+1][1])
                    : "r"(addr));
            }
            #pragma unroll
            for (int mi = 0; mi < 4; mi++)
                #pragma unroll
                for (int nj = 0; nj < 4; nj++)
                    asm volatile(
                        "mma.sync.aligned.m16n8k16.row.col.f32.bf16.bf16.f32 "
                        "{%0,%1,%2,%3}, {%4,%5,%6,%7}, {%8,%9}, {%0,%1,%2,%3};"
                        : "+f"(acc[mi][nj][0]), "+f"(acc[mi][nj][1]),
                          "+f"(acc[mi][nj][2]), "+f"(acc[mi][nj][3])
                        : "r"(af[mi][0]), "r"(af[mi][1]), "r"(af[mi][2]), "r"(af[mi][3]),
                          "r"(bfr[nj][0]), "r"(bfr[nj][1]));
        }
        buf++; if (buf == 3) buf = 0;
    }

    // Epilogue: store exp(logit + bias), fused partial sum(exp)
    float* Mb = g_M + (size_t)b * CHW;
    float esum = 0.f;
    #pragma unroll
    for (int mi = 0; mi < 4; mi++) {
        int r0 = mo + m_base + mi * 16 + (lid >> 2);
        float b0 = bias[r0], b1 = bias[r0 + 8];
        #pragma unroll
        for (int nj = 0; nj < 4; nj++) {
            int col = bn + n_base + nj * 8 + (lid & 3) * 2;
            float e00 = __expf(acc[mi][nj][0] + b0);
            float e01 = __expf(acc[mi][nj][1] + b0);
            float e10 = __expf(acc[mi][nj][2] + b1);
            float e11 = __expf(acc[mi][nj][3] + b1);
            esum += e00 + e01 + e10 + e11;
            *(float2*)(Mb + (size_t)r0 * NHW + col) = make_float2(e00, e01);
            *(float2*)(Mb + (size_t)(r0 + 8) * NHW + col) = make_float2(e10, e11);
        }
    }
    __syncthreads();                 // all async groups done; safe to reuse smem
    float* red = (float*)dynsmem;
    red[tid] = esum;
    __syncthreads();
    for (int s = 128; s > 0; s >>= 1) {
        if (tid < s) red[tid] += red[tid + s];
        __syncthreads();
    }
    if (tid == 0)
        g_part[b * 8 + blockIdx.y * 2 + blockIdx.x] = red[0];
}

// ---------------------------------------------------------------------------
// 2) Prototypes with fused mask: s[m,d] = mean over shots,hw of x*Me*inv_sb
// ---------------------------------------------------------------------------
__global__ void protos(const float* __restrict__ x) {
    __shared__ float inv_sm[SHOTN];
    __shared__ float sdata[128];
    const int m = blockIdx.x;
    const int d = blockIdx.y;

    if (threadIdx.x < SHOTN) {
        float s = 0.f;
        #pragma unroll
        for (int t = 0; t < 8; t++) s += g_part[(m * 20 + threadIdx.x) * 8 + t];
        inv_sm[threadIdx.x] = 1.f / s;
    }
    __syncthreads();

    float sum = 0.f;
    for (int l = threadIdx.x; l < SHOTN * NHW; l += 128) {
        int sb = l >> 8, hw = l & 255;
        size_t idx = (size_t)(m * 20 + sb) * CHW + (size_t)d * NHW + hw;
        sum += x[idx] * g_M[idx] * inv_sm[sb];
    }
    sdata[threadIdx.x] = sum;
    __syncthreads();
    for (int s = 64; s > 0; s >>= 1) {
        if (threadIdx.x < s) sdata[threadIdx.x] += sdata[threadIdx.x + s];
        __syncthreads();
    }
    if (threadIdx.x == 0)
        g_s[m * NC + d] = sdata[0] * (1.f / (SHOTN * NHW));
}

// ---------------------------------------------------------------------------
// 3) Cosine scores + class softmax + spatial mean. 1 block (1024 thr) / query.
//    Mask normalizer cancels in cosine -> qv = x * exp(M), no inv needed.
// ---------------------------------------------------------------------------
__global__ void __launch_bounds__(1024) scores_kernel(const float* __restrict__ x,
                                                      float* __restrict__ out) {
    __shared__ float s_sm[WAYN * NC];        // 10 KB
    __shared__ float sn_sm[WAYN];
    __shared__ float part[6][4][256];        // 24 KB
    __shared__ float red[256];

    const int n  = blockIdx.x;
    const int m0 = n / 15;
    const int qi = n - m0 * 15;
    const int bq = m0 * 20 + SHOTN + qi;
    const int tid = threadIdx.x;

    for (int l = tid; l < WAYN * NC; l += 1024) s_sm[l] = g_s[l];
    __syncthreads();

    // warps 0..4: warp w reduces ||s[w]||
    const int wid = tid >> 5, lid = tid & 31;
    if (wid < WAYN) {
        float a = 0.f;
        #pragma unroll
        for (int j = 0; j < NC / 32; j++) {
            float v = s_sm[wid * NC + j * 32 + lid];
            a += v * v;
        }
        #pragma unroll
        for (int o = 16; o > 0; o >>= 1)
            a += __shfl_xor_sync(0xffffffff, a, o);
        if (lid == 0) sn_sm[wid] = fmaxf(sqrtf(a), EPSF);
    }

    const int f = tid & 255;
    const int slice = tid >> 8;              // 0..3
    const float* xb = x + (size_t)bq * CHW;
    const float* Mb = g_M + (size_t)bq * CHW;

    float dot[WAYN] = {};
    float q2 = 0.f;
    const int d0 = slice * 128;
    for (int d = d0; d < d0 + 128; d++) {
        size_t idx = (size_t)d * NHW + f;
        float qv = xb[idx] * Mb[idx];
        q2 += qv * qv;
        #pragma unroll
        for (int m = 0; m < WAYN; m++)
            dot[m] += qv * s_sm[m * NC + d];
    }
    part[0][slice][f] = q2;
    #pragma unroll
    for (int m = 0; m < WAYN; m++) part[1 + m][slice][f] = dot[m];
    __syncthreads();

    float eprob[WAYN];
    if (slice == 0) {
        q2 = part[0][0][f] + part[0][1][f] + part[0][2][f] + part[0][3][f];
        #pragma unroll
        for (int m = 0; m < WAYN; m++)
            dot[m] = part[1+m][0][f] + part[1+m][1][f] + part[1+m][2][f] + part[1+m][3][f];
        const float qn = fmaxf(sqrtf(q2), EPSF);
        float sc[WAYN], mxv = -3.4e38f;
        #pragma unroll
        for (int m = 0; m < WAYN; m++) {
            sc[m] = SCALEF * dot[m] / (qn * sn_sm[m]);
            mxv = fmaxf(mxv, sc[m]);
        }
        float ssum = 0.f;
        #pragma unroll
        for (int m = 0; m < WAYN; m++) { eprob[m] = __expf(sc[m] - mxv); ssum += eprob[m]; }
        const float inv = 1.f / ssum;
        #pragma unroll
        for (int m = 0; m < WAYN; m++) eprob[m] *= inv;
    }

    for (int m = 0; m < WAYN; m++) {
        __syncthreads();
        if (slice == 0) red[f] = eprob[m];
        __syncthreads();
        for (int st = 128; st > 0; st >>= 1) {
            if (tid < st) red[tid] += red[tid + st];
            __syncthreads();
        }
        if (tid == 0) out[n * WAYN + m] = red[0] * (1.f / NHW);
    }
}

// ---------------------------------------------------------------------------
extern "C" void kernel_launch(void* const* d_in, const int* in_sizes, int n_in,
                              void* d_out, int out_size) {
    const float* x    = (const float*)d_in[0];   // (100, 512, 16, 16)
    const float* Wm   = (const float*)d_in[1];   // (512, 512)
    const float* bias = (const float*)d_in[2];   // (512,)
    float* out = (float*)d_out;                  // (75, 5)

    static int smem_set = 0;
    if (!smem_set) {
        cudaFuncSetAttribute(gemm_tc, cudaFuncAttributeMaxDynamicSharedMemorySize, GEMM_SMEM);
        smem_set = 1;
    }

    const int half_elems = NB * CHW / 2;
    split_w<<<NC * NC / 1024, 256>>>(Wm);
    split_x<<<half_elems / 1024, 256>>>(x, 0);
    split_x<<<half_elems / 1024, 256>>>(x, half_elems);
    gemm_tc<<<dim3(NHW / 128, NC / 128, NB), 256, GEMM_SMEM>>>(bias);  // 4th launch
    protos<<<dim3(WAYN, NC), 128>>>(x);
    scores_kernel<<<NQ, 1024>>>(x, out);
}